// round 10
// baseline (speedup 1.0000x reference)
#include <cuda_runtime.h>
#include <cuda_bf16.h>
#include <math.h>
#include <stdint.h>

// Problem constants: B=8, N=4096, C=768, H=8, D=96
constexpr int M_TOK = 8 * 4096;   // 32768 tokens
constexpr int K_IN  = 768;        // C

// ---- device scratch (allocation-free rule: __device__ globals) ----
__device__ __align__(16) __nv_bfloat16 g_Wrh[96 * 768];  // hi(w1*sum_h Wv_rgb)
__device__ __align__(16) __nv_bfloat16 g_Wrl[96 * 768];  // lo
__device__ __align__(16) __nv_bfloat16 g_Wdh[96 * 768];  // hi(w0*sum_h Wv_depth)
__device__ __align__(16) __nv_bfloat16 g_Wdl[96 * 768];
__device__ __align__(16) __nv_bfloat16 g_Wfh[768 * 96];  // hi(sum_q Wout folded)
__device__ __align__(16) __nv_bfloat16 g_Wfl[768 * 96];
__device__ float g_bg[96];                                // combined bias for g

// ============================================================
// Helpers (plain sm_103-safe PTX: ldmatrix + mma.sync + cp.async)
// ============================================================
__device__ __forceinline__ uint32_t smem_u32(const void* p) {
    uint32_t a;
    asm("{ .reg .u64 t; cvta.to.shared.u64 t, %1; cvt.u32.u64 %0, t; }" : "=r"(a) : "l"(p));
    return a;
}
__device__ __forceinline__ void ldsm4(uint32_t* r, uint32_t addr) {
    asm volatile("ldmatrix.sync.aligned.m8n8.x4.shared.b16 {%0,%1,%2,%3}, [%4];"
                 : "=r"(r[0]), "=r"(r[1]), "=r"(r[2]), "=r"(r[3]) : "r"(addr));
}
__device__ __forceinline__ void mma16816(float* c, const uint32_t* a, const uint32_t* b) {
    asm("mma.sync.aligned.m16n8k16.row.col.f32.bf16.bf16.f32 "
        "{%0,%1,%2,%3}, {%4,%5,%6,%7}, {%8,%9}, {%0,%1,%2,%3};"
        : "+f"(c[0]), "+f"(c[1]), "+f"(c[2]), "+f"(c[3])
        : "r"(a[0]), "r"(a[1]), "r"(a[2]), "r"(a[3]), "r"(b[0]), "r"(b[1]));
}
__device__ __forceinline__ void cpa8(uint32_t d, const void* s) {
    asm volatile("cp.async.ca.shared.global [%0], [%1], 8;" :: "r"(d), "l"(s));
}
__device__ __forceinline__ void cpa16(uint32_t d, const void* s) {
    asm volatile("cp.async.cg.shared.global [%0], [%1], 16;" :: "r"(d), "l"(s));
}
#define CPA_COMMIT() asm volatile("cp.async.commit_group;" ::: "memory")
#define CPA_WAIT0()  asm volatile("cp.async.wait_group 0;" ::: "memory")

__device__ __forceinline__ void splitbf(float v, __nv_bfloat16& h, __nv_bfloat16& l) {
    h = __float2bfloat16_rn(v);
    l = __float2bfloat16_rn(v - __bfloat162float(h));
}
// Fast RZ split of TWO floats -> (hi bf16x2, lo bf16x2).
__device__ __forceinline__ void split2(float x, float y, uint32_t& hi2, uint32_t& lo2) {
    uint32_t bx = __float_as_uint(x), by = __float_as_uint(y);
    hi2 = __byte_perm(bx, by, 0x7632);                 // {hi(x), hi(y)}
    float hx = __uint_as_float(bx & 0xFFFF0000u);
    float hy = __uint_as_float(by & 0xFFFF0000u);
    asm("cvt.rn.bf16x2.f32 %0, %1, %2;" : "=r"(lo2) : "f"(y - hy), "f"(x - hx));
}
// XOR swizzle on 16B chunks: conflict-free ldmatrix for 64B/192B rows
__device__ __forceinline__ uint32_t swz(uint32_t row, uint32_t chunk) {
    return chunk ^ ((row >> 1) & 3);
}

// ============================================================
// Prep: fold heads, sigmoid weights, split to bf16 hi/lo (RN)
// ============================================================
__global__ void prep_kernel(const float* __restrict__ W1, const float* __restrict__ b1,
                            const float* __restrict__ W2, const float* __restrict__ b2,
                            const float* __restrict__ Wout, const float* __restrict__ aw)
{
    int idx = blockIdx.x * blockDim.x + threadIdx.x;   // 0 .. 73727
    float w0 = 1.0f / (1.0f + expf(-aw[0]));
    float w1 = 1.0f / (1.0f + expf(-aw[1]));

    if (idx < 96 * 768) {
        int d = idx / 768;
        int c = idx - d * 768;
        float sr = 0.0f, sd = 0.0f;
#pragma unroll
        for (int h = 0; h < 8; h++) {
            sr += W1[(size_t)(1536 + h * 96 + d) * 768 + c];
            sd += W2[(size_t)(768  + h * 96 + d) * 768 + c];
        }
        __nv_bfloat16 h16, l16;
        splitbf(w1 * sr, h16, l16); g_Wrh[idx] = h16; g_Wrl[idx] = l16;
        splitbf(w0 * sd, h16, l16); g_Wdh[idx] = h16; g_Wdl[idx] = l16;
    }
    if (idx < 768 * 96) {
        int c = idx / 96;
        int d = idx - c * 96;
        float s = 0.0f;
#pragma unroll
        for (int q = 0; q < 8; q++) s += Wout[(size_t)c * 768 + q * 96 + d];
        __nv_bfloat16 h16, l16;
        splitbf(s, h16, l16); g_Wfh[idx] = h16; g_Wfl[idx] = l16;
    }
    if (idx < 96) {
        float sbr = 0.0f, sbd = 0.0f;
#pragma unroll
        for (int h = 0; h < 8; h++) {
            sbr += b1[1536 + h * 96 + idx];
            sbd += b2[768  + h * 96 + idx];
        }
        g_bg[idx] = w0 * sbd + w1 * sbr;
    }
}

// ============================================================
// FUSED kernel. R9: BK=64 stages built from two BK=32 subtiles
// (same 64B-row swizzle); ONE barrier per 64-k slice (48 -> 24).
// ============================================================
constexpr uint32_t SUB  = 28672;           // one BK=32 subtile bundle
constexpr uint32_t BUF  = 2 * SUB;         // one BK=64 stage buffer
constexpr uint32_t G_AL = 8192, G_BH = 16384, G_BL = 22528;
constexpr int G_STAGES  = 24;              // 1536 / 64

constexpr uint32_t P2_GL  = 24576;   // G lo offset (G hi at 0)
constexpr uint32_t P2_B   = 49152;   // B buffers start
constexpr uint32_t P2_BSZ = 24576;   // per B buffer (Bh 12K + Bl 12K)
constexpr uint32_t P2_BL  = 12288;   // Bl offset within a B buffer
constexpr int FUSED_SMEM  = 2 * BUF; // 114688 (phase2 needs 98304 <= this)

__global__ __launch_bounds__(256, 2) void fused_gemm(const float* __restrict__ Xr,
                                                     const float* __restrict__ Xd,
                                                     float* __restrict__ out_rgb,
                                                     const float* __restrict__ bout,
                                                     float* __restrict__ Y)
{
    extern __shared__ char dsm[];
    const uint32_t sbase = smem_u32(dsm);

    const int tid   = threadIdx.x;
    const int lane  = tid & 31;
    const int wid   = tid >> 5;
    const int warpM = wid >> 1;      // 0..3
    const int warpN = wid & 1;       // 0..1
    const int bm    = blockIdx.x << 7;

    // ======================= PHASE 1 =======================
    float acc[2][6][4];
#pragma unroll
    for (int i = 0; i < 2; i++)
#pragma unroll
        for (int j = 0; j < 6; j++)
#pragma unroll
            for (int q = 0; q < 4; q++) acc[i][j][q] = 0.0f;

    const int arow0 = tid >> 3;          // + 32*l  (A: 128 rows x 8 float4-cols per subtile)
    const int ac4   = tid & 7;
    const int brow0 = tid >> 3;          // + 32*l, l<3 (B: 96 rows x 8 uint2-cols per subtile)
    const int bu    = tid & 7;

    const uint32_t a_sts_sw = (swz((uint32_t)arow0, (uint32_t)(ac4 >> 1)) << 4) + (ac4 & 1) * 8;
    const uint32_t b_sts_sw = (swz((uint32_t)brow0, (uint32_t)(bu >> 1)) << 4) + (bu & 1) * 8;

    const uint32_t a_row = (uint32_t)(warpM * 32 + (lane & 15));
    const uint32_t a_ck0 = (uint32_t)(lane >> 4);
    const uint32_t b_row = (uint32_t)(warpN * 48 + (lane & 7) + ((lane >> 4) << 3));
    const uint32_t b_ck0 = (uint32_t)((lane >> 3) & 1);

    float4 av[4];

    // ---- A batch store helper pattern (macro-free, inlined twice) ----
    // ---- prologue: stage 0 (rgb, k 0..63) ----
    {
        // B: both subtiles of stage 0 via cp.async
#pragma unroll
        for (int l = 0; l < 3; l++) {
            uint32_t row = (uint32_t)(brow0 + 32 * l);
            size_t gi = (size_t)row * 768 + (bu << 2);
            cpa8(sbase + G_BH + row * 64 + b_sts_sw,        g_Wrh + gi);
            cpa8(sbase + G_BL + row * 64 + b_sts_sw,        g_Wrl + gi);
            cpa8(sbase + SUB + G_BH + row * 64 + b_sts_sw,  g_Wrh + gi + 32);
            cpa8(sbase + SUB + G_BL + row * 64 + b_sts_sw,  g_Wrl + gi + 32);
        }
        CPA_COMMIT();
        // A batch 1 (k 0..31)
#pragma unroll
        for (int l = 0; l < 4; l++)
            av[l] = *reinterpret_cast<const float4*>(
                Xr + (size_t)(bm + arow0 + 32 * l) * 768 + (ac4 << 2));
#pragma unroll
        for (int l = 0; l < 4; l++) {
            uint32_t ro = (uint32_t)(arow0 + 32 * l) * 64;
            uint32_t h01, l01, h23, l23;
            split2(av[l].x, av[l].y, h01, l01);
            split2(av[l].z, av[l].w, h23, l23);
            *reinterpret_cast<uint2*>(dsm + ro + a_sts_sw)        = make_uint2(h01, h23);
            *reinterpret_cast<uint2*>(dsm + G_AL + ro + a_sts_sw) = make_uint2(l01, l23);
            *reinterpret_cast<float4*>(
                out_rgb + (size_t)(bm + arow0 + 32 * l) * 768 + (ac4 << 2)) = av[l];
        }
        // A batch 2 (k 32..63)
#pragma unroll
        for (int l = 0; l < 4; l++)
            av[l] = *reinterpret_cast<const float4*>(
                Xr + (size_t)(bm + arow0 + 32 * l) * 768 + 32 + (ac4 << 2));
#pragma unroll
        for (int l = 0; l < 4; l++) {
            uint32_t ro = (uint32_t)(arow0 + 32 * l) * 64;
            uint32_t h01, l01, h23, l23;
            split2(av[l].x, av[l].y, h01, l01);
            split2(av[l].z, av[l].w, h23, l23);
            *reinterpret_cast<uint2*>(dsm + SUB + ro + a_sts_sw)        = make_uint2(h01, h23);
            *reinterpret_cast<uint2*>(dsm + SUB + G_AL + ro + a_sts_sw) = make_uint2(l01, l23);
            *reinterpret_cast<float4*>(
                out_rgb + (size_t)(bm + arow0 + 32 * l) * 768 + 32 + (ac4 << 2)) = av[l];
        }
        CPA_WAIT0();
        __syncthreads();
    }

    for (int s = 0; s < G_STAGES; s++) {
        const int sn = s + 1;
        const bool have_next = (sn < G_STAGES);
        const float* Xn = (sn < 12) ? Xr : Xd;
        const __nv_bfloat16* BHn = (sn < 12) ? g_Wrh : g_Wdh;
        const __nv_bfloat16* BLn = (sn < 12) ? g_Wrl : g_Wdl;
        const int kbn = ((sn < 12) ? sn : (sn - 12)) << 6;
        const uint32_t bon = (uint32_t)(sn & 1) * BUF;

        if (have_next) {
            // B stage s+1 (both subtiles) via cp.async
#pragma unroll
            for (int l = 0; l < 3; l++) {
                uint32_t row = (uint32_t)(brow0 + 32 * l);
                size_t gi = (size_t)row * 768 + kbn + (bu << 2);
                cpa8(sbase + bon + G_BH + row * 64 + b_sts_sw,       BHn + gi);
                cpa8(sbase + bon + G_BL + row * 64 + b_sts_sw,       BLn + gi);
                cpa8(sbase + bon + SUB + G_BH + row * 64 + b_sts_sw, BHn + gi + 32);
                cpa8(sbase + bon + SUB + G_BL + row * 64 + b_sts_sw, BLn + gi + 32);
            }
            CPA_COMMIT();
            // A batch 1 of stage s+1
#pragma unroll
            for (int l = 0; l < 4; l++)
                av[l] = *reinterpret_cast<const float4*>(
                    Xn + (size_t)(bm + arow0 + 32 * l) * 768 + kbn + (ac4 << 2));
        }

        // ---- compute subtile 0 of stage s ----
        {
            const uint32_t sb = sbase + (uint32_t)(s & 1) * BUF;
#pragma unroll
            for (int kk = 0; kk < 2; kk++) {
                uint32_t ah[2][4], al[2][4];
#pragma unroll
                for (int mt = 0; mt < 2; mt++) {
                    uint32_t row = a_row + mt * 16;
                    uint32_t addr = sb + row * 64 + (swz(row, kk * 2 + a_ck0) << 4);
                    ldsm4(ah[mt], addr);
                    ldsm4(al[mt], addr + G_AL);
                }
                uint32_t bh2[3][4], bl2[3][4];
#pragma unroll
                for (int ng = 0; ng < 3; ng++) {
                    uint32_t row = b_row + ng * 16;
                    uint32_t addr = sb + G_BH + row * 64 + (swz(row, kk * 2 + b_ck0) << 4);
                    ldsm4(bh2[ng], addr);
                    ldsm4(bl2[ng], addr + (G_BL - G_BH));
                }
#pragma unroll
                for (int mt = 0; mt < 2; mt++)
#pragma unroll
                    for (int nt = 0; nt < 6; nt++)
                        mma16816(acc[mt][nt], ah[mt], &bh2[nt >> 1][(nt & 1) * 2]);
#pragma unroll
                for (int mt = 0; mt < 2; mt++)
#pragma unroll
                    for (int nt = 0; nt < 6; nt++)
                        mma16816(acc[mt][nt], ah[mt], &bl2[nt >> 1][(nt & 1) * 2]);
#pragma unroll
                for (int mt = 0; mt < 2; mt++)
#pragma unroll
                    for (int nt = 0; nt < 6; nt++)
                        mma16816(acc[mt][nt], al[mt], &bh2[nt >> 1][(nt & 1) * 2]);
            }
        }

        if (have_next) {
            // STS A batch 1 -> buf(s+1).sub0 (+ passthrough), then LDG batch 2
            char* st = dsm + bon;
#pragma unroll
            for (int l = 0; l < 4; l++) {
                uint32_t ro = (uint32_t)(arow0 + 32 * l) * 64;
                uint32_t h01, l01, h23, l23;
                split2(av[l].x, av[l].y, h01, l01);
                split2(av[l].z, av[l].w, h23, l23);
                *reinterpret_cast<uint2*>(st + ro + a_sts_sw)        = make_uint2(h01, h23);
                *reinterpret_cast<uint2*>(st + G_AL + ro + a_sts_sw) = make_uint2(l01, l23);
            }
            if (sn < 12) {
#pragma unroll
                for (int l = 0; l < 4; l++)
                    *reinterpret_cast<float4*>(
                        out_rgb + (size_t)(bm + arow0 + 32 * l) * 768 + kbn + (ac4 << 2)) = av[l];
            }
#pragma unroll
            for (int l = 0; l < 4; l++)
                av[l] = *reinterpret_cast<const float4*>(
                    Xn + (size_t)(bm + arow0 + 32 * l) * 768 + kbn + 32 + (ac4 << 2));
        }

        // ---- compute subtile 1 of stage s ----
        {
            const uint32_t sb = sbase + (uint32_t)(s & 1) * BUF + SUB;
#pragma unroll
            for (int kk = 0; kk < 2; kk++) {
                uint32_t ah[2][4], al[2][4];
#pragma unroll
                for (int mt = 0; mt < 2; mt++) {
                    uint32_t row = a_row + mt * 16;
                    uint32_t addr = sb + row * 64 + (swz(row, kk * 2 + a_ck0) << 4);
                    ldsm4(ah[mt], addr);
                    ldsm4(al[mt], addr + G_AL);
                }
                uint32_t bh2[3][4], bl2[3][4];
#pragma unroll
                for (int ng = 0; ng < 3; ng++) {
                    uint32_t row = b_row + ng * 16;
                    uint32_t addr = sb + G_BH + row * 64 + (swz(row, kk * 2 + b_ck0) << 4);
                    ldsm4(bh2[ng], addr);
                    ldsm4(bl2[ng], addr + (G_BL - G_BH));
                }
#pragma unroll
                for (int mt = 0; mt < 2; mt++)
#pragma unroll
                    for (int nt = 0; nt < 6; nt++)
                        mma16816(acc[mt][nt], ah[mt], &bh2[nt >> 1][(nt & 1) * 2]);
#pragma unroll
                for (int mt = 0; mt < 2; mt++)
#pragma unroll
                    for (int nt = 0; nt < 6; nt++)
                        mma16816(acc[mt][nt], ah[mt], &bl2[nt >> 1][(nt & 1) * 2]);
#pragma unroll
                for (int mt = 0; mt < 2; mt++)
#pragma unroll
                    for (int nt = 0; nt < 6; nt++)
                        mma16816(acc[mt][nt], al[mt], &bh2[nt >> 1][(nt & 1) * 2]);
            }
        }

        if (have_next) {
            // STS A batch 2 -> buf(s+1).sub1 (+ passthrough)
            char* st = dsm + bon + SUB;
#pragma unroll
            for (int l = 0; l < 4; l++) {
                uint32_t ro = (uint32_t)(arow0 + 32 * l) * 64;
                uint32_t h01, l01, h23, l23;
                split2(av[l].x, av[l].y, h01, l01);
                split2(av[l].z, av[l].w, h23, l23);
                *reinterpret_cast<uint2*>(st + ro + a_sts_sw)        = make_uint2(h01, h23);
                *reinterpret_cast<uint2*>(st + G_AL + ro + a_sts_sw) = make_uint2(l01, l23);
            }
            if (sn < 12) {
#pragma unroll
                for (int l = 0; l < 4; l++)
                    *reinterpret_cast<float4*>(
                        out_rgb + (size_t)(bm + arow0 + 32 * l) * 768 + kbn + 32 + (ac4 << 2)) = av[l];
            }
            CPA_WAIT0();
        }
        __syncthreads();
    }

    // ============== PHASE 1 -> 2 TRANSITION ==============
#pragma unroll
    for (int l = 0; l < 3; l++) {
        int f = tid + (l << 8);
        int r = f / 12, u = f - r * 12;
        uint32_t so = (uint32_t)r * 192 + (swz((uint32_t)r, (uint32_t)u) << 4);
        cpa16(sbase + P2_B + so,         g_Wfh + (size_t)r * 96 + (u << 3));
        cpa16(sbase + P2_B + P2_BL + so, g_Wfl + (size_t)r * 96 + (u << 3));
    }
    CPA_COMMIT();

    // Write G block (hi/lo, bias added) into smem [0, 49152).
#pragma unroll
    for (int mt = 0; mt < 2; mt++) {
        uint32_t r0 = (uint32_t)(warpM * 32 + mt * 16 + (lane >> 2));
#pragma unroll
        for (int nt = 0; nt < 6; nt++) {
            int n = warpN * 48 + nt * 8 + (lane & 3) * 2;
            float b0 = g_bg[n], b1 = g_bg[n + 1];
            float v0 = acc[mt][nt][0] + b0, v1 = acc[mt][nt][1] + b1;
            float v2 = acc[mt][nt][2] + b0, v3 = acc[mt][nt][3] + b1;
            uint32_t u = (uint32_t)(warpN * 6 + nt);
            uint32_t off = (uint32_t)((lane & 3) << 2);
            uint32_t ad0 = r0 * 192 + (swz(r0, u) << 4) + off;
            uint32_t ad1 = (r0 + 8) * 192 + (swz(r0 + 8, u) << 4) + off;
            uint32_t h2, l2;
            split2(v0, v1, h2, l2);
            *reinterpret_cast<uint32_t*>(dsm + ad0)         = h2;
            *reinterpret_cast<uint32_t*>(dsm + P2_GL + ad0) = l2;
            split2(v2, v3, h2, l2);
            *reinterpret_cast<uint32_t*>(dsm + ad1)         = h2;
            *reinterpret_cast<uint32_t*>(dsm + P2_GL + ad1) = l2;
        }
    }
    CPA_WAIT0();
    __syncthreads();

    // ======================= PHASE 2 =======================
    const uint32_t p2b_row = (uint32_t)(warpN * 32 + (lane & 7) + ((lane >> 4) << 3));
    const uint32_t p2b_ck0 = (uint32_t)((lane >> 3) & 1);

    for (int i = 0; i < 12; i++) {
        if (i + 1 < 12) {
            const int cn = (i + 1) << 6;
            const uint32_t bo = P2_B + (uint32_t)((i + 1) & 1) * P2_BSZ;
#pragma unroll
            for (int l = 0; l < 3; l++) {
                int f = tid + (l << 8);
                int r = f / 12, u = f - r * 12;
                uint32_t so = (uint32_t)r * 192 + (swz((uint32_t)r, (uint32_t)u) << 4);
                cpa16(sbase + bo + so,         g_Wfh + (size_t)(cn + r) * 96 + (u << 3));
                cpa16(sbase + bo + P2_BL + so, g_Wfl + (size_t)(cn + r) * 96 + (u << 3));
            }
            CPA_COMMIT();
        }

        float acc2[2][4][4];
#pragma unroll
        for (int a = 0; a < 2; a++)
#pragma unroll
            for (int j = 0; j < 4; j++)
#pragma unroll
                for (int q = 0; q < 4; q++) acc2[a][j][q] = 0.0f;

        const uint32_t bbase = sbase + P2_B + (uint32_t)(i & 1) * P2_BSZ;
#pragma unroll
        for (int ks = 0; ks < 6; ks++) {
            uint32_t ah[2][4], al[2][4];
#pragma unroll
            for (int mt = 0; mt < 2; mt++) {
                uint32_t row = a_row + mt * 16;
                uint32_t addr = sbase + row * 192 + (swz(row, ks * 2 + a_ck0) << 4);
                ldsm4(ah[mt], addr);
                ldsm4(al[mt], addr + P2_GL);
            }
            uint32_t bh2[2][4], bl2[2][4];
#pragma unroll
            for (int ng = 0; ng < 2; ng++) {
                uint32_t row = p2b_row + ng * 16;
                uint32_t addr = bbase + row * 192 + (swz(row, ks * 2 + p2b_ck0) << 4);
                ldsm4(bh2[ng], addr);
                ldsm4(bl2[ng], addr + P2_BL);
            }
#pragma unroll
            for (int mt = 0; mt < 2; mt++)
#pragma unroll
                for (int nt = 0; nt < 4; nt++)
                    mma16816(acc2[mt][nt], ah[mt], &bh2[nt >> 1][(nt & 1) * 2]);
#pragma unroll
            for (int mt = 0; mt < 2; mt++)
#pragma unroll
                for (int nt = 0; nt < 4; nt++)
                    mma16816(acc2[mt][nt], ah[mt], &bl2[nt >> 1][(nt & 1) * 2]);
#pragma unroll
            for (int mt = 0; mt < 2; mt++)
#pragma unroll
                for (int nt = 0; nt < 4; nt++)
                    mma16816(acc2[mt][nt], al[mt], &bh2[nt >> 1][(nt & 1) * 2]);
        }

        // epilogue tile i
#pragma unroll
        for (int mt = 0; mt < 2; mt++) {
            int m0 = bm + warpM * 32 + mt * 16 + (lane >> 2);
#pragma unroll
            for (int nt = 0; nt < 4; nt++) {
                int n = (i << 6) + warpN * 32 + nt * 8 + (lane & 3) * 2;
                float b0 = bout[n], b1 = bout[n + 1];
                *reinterpret_cast<float2*>(Y + (size_t)m0 * 768 + n) =
                    make_float2(acc2[mt][nt][0] + b0, acc2[mt][nt][1] + b1);
                *reinterpret_cast<float2*>(Y + (size_t)(m0 + 8) * 768 + n) =
                    make_float2(acc2[mt][nt][2] + b0, acc2[mt][nt][3] + b1);
            }
        }

        if (i + 1 < 12) CPA_WAIT0();
        __syncthreads();
    }
}

// ============================================================
extern "C" void kernel_launch(void* const* d_in, const int* in_sizes, int n_in,
                              void* d_out, int out_size)
{
    const float* x_rgb   = (const float*)d_in[0];
    const float* x_depth = (const float*)d_in[1];
    const float* W1      = (const float*)d_in[2];
    const float* b1      = (const float*)d_in[3];
    const float* W2      = (const float*)d_in[4];
    const float* b2      = (const float*)d_in[5];
    const float* Wout    = (const float*)d_in[6];
    const float* bout    = (const float*)d_in[7];
    const float* aw      = (const float*)d_in[8];

    float* out_rgb = (float*)d_out;
    float* out_fus = out_rgb + (size_t)M_TOK * K_IN;   // second half: x_fusion

    static bool attr_done = false;
    if (!attr_done) {
        cudaFuncSetAttribute(fused_gemm, cudaFuncAttributeMaxDynamicSharedMemorySize,
                             FUSED_SMEM);
        attr_done = true;
    }

    prep_kernel<<<288, 256>>>(W1, b1, W2, b2, Wout, aw);
    fused_gemm<<<M_TOK / 128, 256, FUSED_SMEM>>>(x_rgb, x_depth, out_rgb, bout, out_fus);
}